// round 8
// baseline (speedup 1.0000x reference)
#include <cuda_runtime.h>
#include <math_constants.h>

// EMDLoss (Sinkhorn, eps=0.005, 50 iters), B=8, N=2048, dim=3.
// Morton-sorted sets; log2-domain factored cost. Fast iterations build a
// per-warp 64-bit CHUNK MASK from per-chunk AABBs + per-chunk pot max vs
// the carried row-max threshold, then scan only surviving 32-j chunks.
// All excluded terms are provably below the truncation window.

#define BB 8
#define NN 2048
#define NCH 64

static __device__ float4 d_P4[BB * NN];   // sorted (x,y,z, |p|^2*S2)
static __device__ float4 d_Q4[BB * NN];
static __device__ float  d_f[BB * NN];
static __device__ float  d_g[BB * NN];
static __device__ float  d_mf[BB * NN];
static __device__ float  d_mg[BB * NN];
static __device__ float  d_partials[512];
// chunk AABBs: index (set*BB + b)*NCH + c ; set 0 = P, 1 = Q
static __device__ float  d_bxlo[2 * BB * NCH], d_bxhi[2 * BB * NCH];
static __device__ float  d_bylo[2 * BB * NCH], d_byhi[2 * BB * NCH];
static __device__ float  d_bzlo[2 * BB * NCH], d_bzhi[2 * BB * NCH];

__device__ __forceinline__ float ex2f_(float x) {
    float r; asm("ex2.approx.f32 %0, %1;" : "=f"(r) : "f"(x)); return r;
}
__device__ __forceinline__ float lg2f_(float x) {
    float r; asm("lg2.approx.f32 %0, %1;" : "=f"(r) : "f"(x)); return r;
}

#define S2F      288.5390081777927f      // 1/(eps*ln2)
#define S2X2     577.0780163555854f      // 2/(eps*ln2)
#define EPSLN2   0.0034657359027997f     // eps*ln2
#define EPSLOGMU (-0.03812309493079699f) // eps * (-ln N)
#define TT       25.0f
#define SLACKTT  37.0f                   // SLACK(12) + TT
#define TTL      33.0f                   // loss truncation (log2)

// ---------------------------------------------------------------------------
__global__ void __launch_bounds__(256) prep_sort_kernel(
    const float* __restrict__ preds, const float* __restrict__ gts) {
    int blk = blockIdx.x;
    int b = blk >> 1;
    int set = blk & 1;
    const float* src = set ? gts : preds;
    float4* dst = set ? d_Q4 : d_P4;
    float*  pot = set ? d_g  : d_f;
    int off = b * NN;

    __shared__ unsigned skey[NN];

    for (int i = threadIdx.x; i < NN; i += 256) {
        const float* p = src + (off + i) * 3;
        float x = p[0], y = p[1], z = p[2];
        int ux = (int)floorf((x + 4.f) * 4.f); ux = min(31, max(0, ux));
        int uy = (int)floorf((y + 4.f) * 4.f); uy = min(31, max(0, uy));
        int uz = (int)floorf((z + 4.f) * 4.f); uz = min(31, max(0, uz));
        unsigned key = 0;
#pragma unroll
        for (int bit = 0; bit < 5; ++bit) {
            key |= (((unsigned)ux >> bit) & 1u) << (3 * bit + 2);
            key |= (((unsigned)uy >> bit) & 1u) << (3 * bit + 1);
            key |= (((unsigned)uz >> bit) & 1u) << (3 * bit + 0);
        }
        skey[i] = (key << 11) | (unsigned)i;
    }
    __syncthreads();

    for (int k = 2; k <= NN; k <<= 1) {
        for (int j = k >> 1; j > 0; j >>= 1) {
            for (int i = threadIdx.x; i < NN; i += 256) {
                int l = i ^ j;
                if (l > i) {
                    unsigned a = skey[i], c = skey[l];
                    bool up = ((i & k) == 0);
                    if ((a > c) == up) { skey[i] = c; skey[l] = a; }
                }
            }
            __syncthreads();
        }
    }

    for (int i = threadIdx.x; i < NN; i += 256) {
        int si = (int)(skey[i] & 2047u);
        const float* p = src + (off + si) * 3;
        float x = p[0], y = p[1], z = p[2];
        dst[off + i] = make_float4(x, y, z, (x * x + y * y + z * z) * S2F);
        pot[off + i] = 0.f;
    }
    __syncthreads();

    // per-chunk AABBs (8 warps x 8 chunks)
    {
        int w = threadIdx.x >> 5, l = threadIdx.x & 31;
        int base = (set * BB + b) * NCH;
        for (int i = 0; i < 8; ++i) {
            int c = w * 8 + i;
            float4 q = dst[off + c * 32 + l];
            float xlo = q.x, xhi = q.x, ylo = q.y, yhi = q.y, zlo = q.z, zhi = q.z;
#pragma unroll
            for (int o = 16; o; o >>= 1) {
                xlo = fminf(xlo, __shfl_xor_sync(0xffffffffu, xlo, o));
                xhi = fmaxf(xhi, __shfl_xor_sync(0xffffffffu, xhi, o));
                ylo = fminf(ylo, __shfl_xor_sync(0xffffffffu, ylo, o));
                yhi = fmaxf(yhi, __shfl_xor_sync(0xffffffffu, yhi, o));
                zlo = fminf(zlo, __shfl_xor_sync(0xffffffffu, zlo, o));
                zhi = fmaxf(zhi, __shfl_xor_sync(0xffffffffu, zhi, o));
            }
            if (l == 0) {
                d_bxlo[base + c] = xlo; d_bxhi[base + c] = xhi;
                d_bylo[base + c] = ylo; d_byhi[base + c] = yhi;
                d_bzlo[base + c] = zlo; d_bzhi[base + c] = zhi;
            }
        }
    }
}

// ---------------------------------------------------------------------------
#define MERGEROW(m, s, off)                                         \
    {                                                               \
        float mo = __shfl_xor_sync(0xffffffffu, m, off);            \
        float so = __shfl_xor_sync(0xffffffffu, s, off);            \
        float mn = fmaxf(m, mo);                                    \
        s = fmaf(so, ex2f_(mo - mn), s * ex2f_(m - mn));            \
        m = mn;                                                     \
    }

#define ROWUPD(m, s, mt, a, e)                                      \
    if (__any_sync(0xffffffffu, (e) > 0.f)) {                       \
        if (__any_sync(0xffffffffu, (a) > (m))) {                   \
            float c = fmaxf(m, a);                                  \
            c = fmaxf(c, __shfl_xor_sync(0xffffffffu, c, 16));      \
            c = fmaxf(c, __shfl_xor_sync(0xffffffffu, c, 8));       \
            c = fmaxf(c, __shfl_xor_sync(0xffffffffu, c, 4));       \
            c = fmaxf(c, __shfl_xor_sync(0xffffffffu, c, 2));       \
            c = fmaxf(c, __shfl_xor_sync(0xffffffffu, c, 1));       \
            s = fmaf(s, ex2f_(m - c), ex2f_((a) - c));              \
            m = c; mt = c - TT;                                     \
        } else {                                                    \
            s += ex2f_((a) - m);                                    \
        }                                                           \
    }

// Boot half-update (iteration 0): full online LSE, stores row max.
__global__ void __launch_bounds__(256) half_boot(int dir) {
    int blk = blockIdx.x;
    int b = blk >> 6;
    int chunk = blk & 63;

    const float4* R4  = dir ? d_Q4 : d_P4;
    const float4* D4  = dir ? d_P4 : d_Q4;
    const float*  pin = dir ? d_f  : d_g;
    float*        pout = dir ? d_g : d_f;
    float*        mout = dir ? d_mg : d_mf;

    __shared__ float4 tbl[NN];
    {
        const float4* Db = D4 + b * NN;
        const float*  pb = pin + b * NN;
        for (int j = threadIdx.x; j < NN; j += 256) {
            float4 q = Db[j];
            float4 t;
            t.x = q.x * S2X2;
            t.y = q.y * S2X2;
            t.z = q.z * S2X2;
            t.w = fmaf(pb[j], S2F, -q.w);
            tbl[j] = t;
        }
    }
    __syncthreads();

    int warp = threadIdx.x >> 5;
    int lane = threadIdx.x & 31;
    int row0 = b * NN + chunk * 32 + warp * 4;

    float4 r0 = R4[row0 + 0];
    float4 r1 = R4[row0 + 1];
    float4 r2 = R4[row0 + 2];
    float4 r3 = R4[row0 + 3];

    const float NEGINF = -CUDART_INF_F;
    float m0 = NEGINF, m1 = NEGINF, m2 = NEGINF, m3 = NEGINF;
    float s0 = 0.f, s1 = 0.f, s2 = 0.f, s3 = 0.f;
    float mt0 = NEGINF, mt1 = NEGINF, mt2 = NEGINF, mt3 = NEGINF;

#pragma unroll 2
    for (int k = 0; k < 64; ++k) {
        float4 q = tbl[(k << 5) + lane];
        float a0 = fmaf(r0.x, q.x, fmaf(r0.y, q.y, fmaf(r0.z, q.z, q.w)));
        float a1 = fmaf(r1.x, q.x, fmaf(r1.y, q.y, fmaf(r1.z, q.z, q.w)));
        float a2 = fmaf(r2.x, q.x, fmaf(r2.y, q.y, fmaf(r2.z, q.z, q.w)));
        float a3 = fmaf(r3.x, q.x, fmaf(r3.y, q.y, fmaf(r3.z, q.z, q.w)));
        float e0 = a0 - mt0;
        float e1 = a1 - mt1;
        float e2 = a2 - mt2;
        float e3 = a3 - mt3;
        float emax = fmaxf(fmaxf(e0, e1), fmaxf(e2, e3));
        if (__any_sync(0xffffffffu, emax > 0.f)) {
            ROWUPD(m0, s0, mt0, a0, e0)
            ROWUPD(m1, s1, mt1, a1, e1)
            ROWUPD(m2, s2, mt2, a2, e2)
            ROWUPD(m3, s3, mt3, a3, e3)
        }
    }

#pragma unroll
    for (int o = 16; o; o >>= 1) {
        MERGEROW(m0, s0, o);
        MERGEROW(m1, s1, o);
        MERGEROW(m2, s2, o);
        MERGEROW(m3, s3, o);
    }

    if (lane == 0) {
        pout[row0 + 0] = fmaf(-EPSLN2, (-r0.w) + m0 + lg2f_(s0), EPSLOGMU);
        pout[row0 + 1] = fmaf(-EPSLN2, (-r1.w) + m1 + lg2f_(s1), EPSLOGMU);
        pout[row0 + 2] = fmaf(-EPSLN2, (-r2.w) + m2 + lg2f_(s2), EPSLOGMU);
        pout[row0 + 3] = fmaf(-EPSLN2, (-r3.w) + m3 + lg2f_(s3), EPSLOGMU);
        mout[row0 + 0] = m0;
        mout[row0 + 1] = m1;
        mout[row0 + 2] = m2;
        mout[row0 + 3] = m3;
    }
}

// ---------------------------------------------------------------------------
// Chunk-max of pot*S2 into cmax[] (8 warps x 8 chunks), call before sync.
#define CHUNKMAX(PIN)                                               \
    {                                                               \
        int w_ = threadIdx.x >> 5, l_ = threadIdx.x & 31;           \
        const float* pb_ = (PIN) + b * NN;                          \
        for (int i_ = 0; i_ < 8; ++i_) {                            \
            int c_ = w_ * 8 + i_;                                   \
            float v_ = pb_[c_ * 32 + l_] * S2F;                     \
            for (int o_ = 16; o_; o_ >>= 1)                         \
                v_ = fmaxf(v_, __shfl_xor_sync(0xffffffffu, v_, o_));\
            if (l_ == 0) cmax[c_] = v_;                             \
        }                                                           \
    }

// Build 2x32-bit chunk masks for this warp. RHS = min_i (thr_i - pp_i*S2).
#define BUILD_MASKS(RHS)                                            \
    unsigned mk0, mk1;                                              \
    {                                                               \
        float rlox = fminf(fminf(r0.x, r1.x), fminf(r2.x, r3.x));   \
        float rhix = fmaxf(fmaxf(r0.x, r1.x), fmaxf(r2.x, r3.x));   \
        float rloy = fminf(fminf(r0.y, r1.y), fminf(r2.y, r3.y));   \
        float rhiy = fmaxf(fmaxf(r0.y, r1.y), fmaxf(r2.y, r3.y));   \
        float rloz = fminf(fminf(r0.z, r1.z), fminf(r2.z, r3.z));   \
        float rhiz = fmaxf(fmaxf(r0.z, r1.z), fmaxf(r2.z, r3.z));   \
        int gi0 = tbbase + lane;                                    \
        float dx = fmaxf(0.f, fmaxf(d_bxlo[gi0] - rhix, rlox - d_bxhi[gi0])); \
        float dy = fmaxf(0.f, fmaxf(d_bylo[gi0] - rhiy, rloy - d_byhi[gi0])); \
        float dz = fmaxf(0.f, fmaxf(d_bzlo[gi0] - rhiz, rloz - d_bzhi[gi0])); \
        float d2 = fmaf(dx, dx, fmaf(dy, dy, dz * dz));             \
        mk0 = __ballot_sync(0xffffffffu,                            \
                fmaf(-S2F, d2, cmax[lane]) >= (RHS));               \
        int gi1 = gi0 + 32;                                         \
        dx = fmaxf(0.f, fmaxf(d_bxlo[gi1] - rhix, rlox - d_bxhi[gi1])); \
        dy = fmaxf(0.f, fmaxf(d_bylo[gi1] - rhiy, rloy - d_byhi[gi1])); \
        dz = fmaxf(0.f, fmaxf(d_bzlo[gi1] - rhiz, rloz - d_bzhi[gi1])); \
        d2 = fmaf(dx, dx, fmaf(dy, dy, dz * dz));                   \
        mk1 = __ballot_sync(0xffffffffu,                            \
                fmaf(-S2F, d2, cmax[lane + 32]) >= (RHS));          \
    }

// Fast half-update: masked chunk scan, branch-free inside chunks.
__global__ void __launch_bounds__(256) half_fast(int dir) {
    int blk = blockIdx.x;
    int b = blk >> 6;
    int chunk = blk & 63;

    const float4* R4  = dir ? d_Q4 : d_P4;
    const float4* D4  = dir ? d_P4 : d_Q4;
    const float*  pin = dir ? d_f  : d_g;
    float*        pout = dir ? d_g : d_f;
    float*        marr = dir ? d_mg : d_mf;
    int tbbase = ((dir ? 0 : 1) * BB + b) * NCH;   // table side AABBs

    __shared__ float4 tbl[NN];
    __shared__ float cmax[NCH];
    {
        const float4* Db = D4 + b * NN;
        const float*  pb = pin + b * NN;
        for (int j = threadIdx.x; j < NN; j += 256) {
            float4 q = Db[j];
            float4 t;
            t.x = q.x * S2X2;
            t.y = q.y * S2X2;
            t.z = q.z * S2X2;
            t.w = fmaf(pb[j], S2F, -q.w);
            tbl[j] = t;
        }
    }
    CHUNKMAX(pin)
    __syncthreads();

    int warp = threadIdx.x >> 5;
    int lane = threadIdx.x & 31;
    int row0 = b * NN + chunk * 32 + warp * 4;

    float4 r0 = R4[row0 + 0];
    float4 r1 = R4[row0 + 1];
    float4 r2 = R4[row0 + 2];
    float4 r3 = R4[row0 + 3];

    float muT0 = marr[row0 + 0] - SLACKTT;
    float muT1 = marr[row0 + 1] - SLACKTT;
    float muT2 = marr[row0 + 2] - SLACKTT;
    float muT3 = marr[row0 + 3] - SLACKTT;

    float RHS = fminf(fminf(muT0 - r0.w, muT1 - r1.w),
                      fminf(muT2 - r2.w, muT3 - r3.w));
    BUILD_MASKS(RHS)

    const float NEGINF = -CUDART_INF_F;
    float s0 = 0.f, s1 = 0.f, s2 = 0.f, s3 = 0.f;
    float mx0 = NEGINF, mx1 = NEGINF, mx2 = NEGINF, mx3 = NEGINF;

#pragma unroll
    for (int h = 0; h < 2; ++h) {
        unsigned mm = h ? mk1 : mk0;
        int cb = h << 5;
        while (mm) {
            int c = (__ffs(mm) - 1) + cb;
            mm &= mm - 1;
            float4 q = tbl[(c << 5) + lane];
            float a0 = fmaf(r0.x, q.x, fmaf(r0.y, q.y, fmaf(r0.z, q.z, q.w)));
            float a1 = fmaf(r1.x, q.x, fmaf(r1.y, q.y, fmaf(r1.z, q.z, q.w)));
            float a2 = fmaf(r2.x, q.x, fmaf(r2.y, q.y, fmaf(r2.z, q.z, q.w)));
            float a3 = fmaf(r3.x, q.x, fmaf(r3.y, q.y, fmaf(r3.z, q.z, q.w)));
            mx0 = fmaxf(mx0, a0);
            mx1 = fmaxf(mx1, a1);
            mx2 = fmaxf(mx2, a2);
            mx3 = fmaxf(mx3, a3);
            s0 += ex2f_(a0 - muT0);
            s1 += ex2f_(a1 - muT1);
            s2 += ex2f_(a2 - muT2);
            s3 += ex2f_(a3 - muT3);
        }
    }

#pragma unroll
    for (int o = 16; o; o >>= 1) {
        s0 += __shfl_xor_sync(0xffffffffu, s0, o);
        s1 += __shfl_xor_sync(0xffffffffu, s1, o);
        s2 += __shfl_xor_sync(0xffffffffu, s2, o);
        s3 += __shfl_xor_sync(0xffffffffu, s3, o);
        mx0 = fmaxf(mx0, __shfl_xor_sync(0xffffffffu, mx0, o));
        mx1 = fmaxf(mx1, __shfl_xor_sync(0xffffffffu, mx1, o));
        mx2 = fmaxf(mx2, __shfl_xor_sync(0xffffffffu, mx2, o));
        mx3 = fmaxf(mx3, __shfl_xor_sync(0xffffffffu, mx3, o));
    }

    if (lane == 0) {
        pout[row0 + 0] = fmaf(-EPSLN2, (-r0.w) + muT0 + lg2f_(s0), EPSLOGMU);
        pout[row0 + 1] = fmaf(-EPSLN2, (-r1.w) + muT1 + lg2f_(s1), EPSLOGMU);
        pout[row0 + 2] = fmaf(-EPSLN2, (-r2.w) + muT2 + lg2f_(s2), EPSLOGMU);
        pout[row0 + 3] = fmaf(-EPSLN2, (-r3.w) + muT3 + lg2f_(s3), EPSLOGMU);
        marr[row0 + 0] = mx0;
        marr[row0 + 1] = mx1;
        marr[row0 + 2] = mx2;
        marr[row0 + 3] = mx3;
    }
}

// ---------------------------------------------------------------------------
// Loss with the same chunk masking; threshold a >= -TTL - ff_i.
__global__ void __launch_bounds__(256) loss_kernel() {
    int blk = blockIdx.x;
    int b = blk >> 6;
    int chunk = blk & 63;
    int tbbase = (1 * BB + b) * NCH;   // table = Q

    __shared__ float4 tbl[NN];
    __shared__ float  gg[NN];
    __shared__ float  cmax[NCH];
    {
        const float4* Db = d_Q4 + b * NN;
        const float*  pb = d_g + b * NN;
        for (int j = threadIdx.x; j < NN; j += 256) {
            float4 q = Db[j];
            float gj = pb[j];
            float4 t;
            t.x = q.x * S2X2;
            t.y = q.y * S2X2;
            t.z = q.z * S2X2;
            t.w = fmaf(gj, S2F, -q.w);
            tbl[j] = t;
            gg[j] = gj;
        }
    }
    CHUNKMAX(d_g)
    __syncthreads();

    int warp = threadIdx.x >> 5;
    int lane = threadIdx.x & 31;
    int row0 = b * NN + chunk * 32 + warp * 4;

    float4 r0 = d_P4[row0 + 0];
    float4 r1 = d_P4[row0 + 1];
    float4 r2 = d_P4[row0 + 2];
    float4 r3 = d_P4[row0 + 3];
    float fr0 = d_f[row0 + 0], fr1 = d_f[row0 + 1];
    float fr2 = d_f[row0 + 2], fr3 = d_f[row0 + 3];
    float ff0 = fmaf(fr0, S2F, -r0.w);
    float ff1 = fmaf(fr1, S2F, -r1.w);
    float ff2 = fmaf(fr2, S2F, -r2.w);
    float ff3 = fmaf(fr3, S2F, -r3.w);

    // include chunk if some a_ij >= -TTL - ff_i
    float RHS = fminf(fminf((-TTL - ff0) - r0.w, (-TTL - ff1) - r1.w),
                      fminf((-TTL - ff2) - r2.w, (-TTL - ff3) - r3.w));
    BUILD_MASKS(RHS)

    float part = 0.f;
#pragma unroll
    for (int h = 0; h < 2; ++h) {
        unsigned mm = h ? mk1 : mk0;
        int cb = h << 5;
        while (mm) {
            int c = (__ffs(mm) - 1) + cb;
            mm &= mm - 1;
            int j = (c << 5) + lane;
            float4 q = tbl[j];
            float gj = gg[j];
            {
                float a = fmaf(r0.x, q.x, fmaf(r0.y, q.y, fmaf(r0.z, q.z, q.w)));
                float arg = a + ff0;
                float C = fmaf(-EPSLN2, arg, fr0 + gj);
                part = fmaf(ex2f_(arg), C, part);
            }
            {
                float a = fmaf(r1.x, q.x, fmaf(r1.y, q.y, fmaf(r1.z, q.z, q.w)));
                float arg = a + ff1;
                float C = fmaf(-EPSLN2, arg, fr1 + gj);
                part = fmaf(ex2f_(arg), C, part);
            }
            {
                float a = fmaf(r2.x, q.x, fmaf(r2.y, q.y, fmaf(r2.z, q.z, q.w)));
                float arg = a + ff2;
                float C = fmaf(-EPSLN2, arg, fr2 + gj);
                part = fmaf(ex2f_(arg), C, part);
            }
            {
                float a = fmaf(r3.x, q.x, fmaf(r3.y, q.y, fmaf(r3.z, q.z, q.w)));
                float arg = a + ff3;
                float C = fmaf(-EPSLN2, arg, fr3 + gj);
                part = fmaf(ex2f_(arg), C, part);
            }
        }
    }

    __shared__ float red[256];
    red[threadIdx.x] = part;
    __syncthreads();
#pragma unroll
    for (int o = 128; o; o >>= 1) {
        if (threadIdx.x < o) red[threadIdx.x] += red[threadIdx.x + o];
        __syncthreads();
    }
    if (threadIdx.x == 0) d_partials[blockIdx.x] = red[0];
}

__global__ void reduce_kernel(float* __restrict__ out) {
    __shared__ float red[256];
    float v = 0.f;
    for (int i = threadIdx.x; i < 512; i += 256) v += d_partials[i];
    red[threadIdx.x] = v;
    __syncthreads();
#pragma unroll
    for (int o = 128; o; o >>= 1) {
        if (threadIdx.x < o) red[threadIdx.x] += red[threadIdx.x + o];
        __syncthreads();
    }
    if (threadIdx.x == 0) out[0] = red[0] * 0.125f;
}

extern "C" void kernel_launch(void* const* d_in, const int* in_sizes, int n_in,
                              void* d_out, int out_size) {
    const float* preds = (const float*)d_in[0];
    const float* gts   = (const float*)d_in[1];
    float* out = (float*)d_out;

    prep_sort_kernel<<<BB * 2, 256>>>(preds, gts);
    half_boot<<<BB * 64, 256>>>(0);
    half_boot<<<BB * 64, 256>>>(1);
    for (int it = 1; it < 50; ++it) {
        half_fast<<<BB * 64, 256>>>(0);
        half_fast<<<BB * 64, 256>>>(1);
    }
    loss_kernel<<<BB * 64, 256>>>();
    reduce_kernel<<<1, 256>>>(out);
}

// round 9
// speedup vs baseline: 1.1255x; 1.1255x over previous
#include <cuda_runtime.h>
#include <math_constants.h>

// EMDLoss (Sinkhorn, eps=0.005, 50 iters), B=8, N=2048, dim=3.
// Morton-sorted sets; log2-domain factored cost. Fast iterations are
// BRANCH-FREE (ex2 underflow = truncation) with a carried row-max UPPER
// BOUND (muT + log2 s); grid 1024 via 16-rows-per-block split for occupancy.

#define BB 8
#define NN 2048

static __device__ float4 d_P4[BB * NN];   // sorted (x,y,z, |p|^2*S2)
static __device__ float4 d_Q4[BB * NN];
static __device__ float  d_f[BB * NN];
static __device__ float  d_g[BB * NN];
static __device__ float  d_mf[BB * NN];   // carried row-max bound (a-units)
static __device__ float  d_mg[BB * NN];
static __device__ float  d_partials[1024];

__device__ __forceinline__ float ex2f_(float x) {
    float r; asm("ex2.approx.f32 %0, %1;" : "=f"(r) : "f"(x)); return r;
}
__device__ __forceinline__ float lg2f_(float x) {
    float r; asm("lg2.approx.f32 %0, %1;" : "=f"(r) : "f"(x)); return r;
}

#define S2F      288.5390081777927f      // 1/(eps*ln2)
#define S2X2     577.0780163555854f      // 2/(eps*ln2)
#define EPSLN2   0.0034657359027997f     // eps*ln2
#define EPSLOGMU (-0.03812309493079699f) // eps * (-ln N)
#define TT       25.0f
#define SLACKTT  44.0f                   // TT + bound looseness(5) + drift(14)
#define TTL      33.0f                   // loss truncation (log2)

// ---------------------------------------------------------------------------
__global__ void __launch_bounds__(256) prep_sort_kernel(
    const float* __restrict__ preds, const float* __restrict__ gts) {
    int blk = blockIdx.x;
    int b = blk >> 1;
    int set = blk & 1;
    const float* src = set ? gts : preds;
    float4* dst = set ? d_Q4 : d_P4;
    float*  pot = set ? d_g  : d_f;
    int off = b * NN;

    __shared__ unsigned skey[NN];

    for (int i = threadIdx.x; i < NN; i += 256) {
        const float* p = src + (off + i) * 3;
        float x = p[0], y = p[1], z = p[2];
        int ux = (int)floorf((x + 4.f) * 4.f); ux = min(31, max(0, ux));
        int uy = (int)floorf((y + 4.f) * 4.f); uy = min(31, max(0, uy));
        int uz = (int)floorf((z + 4.f) * 4.f); uz = min(31, max(0, uz));
        unsigned key = 0;
#pragma unroll
        for (int bit = 0; bit < 5; ++bit) {
            key |= (((unsigned)ux >> bit) & 1u) << (3 * bit + 2);
            key |= (((unsigned)uy >> bit) & 1u) << (3 * bit + 1);
            key |= (((unsigned)uz >> bit) & 1u) << (3 * bit + 0);
        }
        skey[i] = (key << 11) | (unsigned)i;
    }
    __syncthreads();

    for (int k = 2; k <= NN; k <<= 1) {
        for (int j = k >> 1; j > 0; j >>= 1) {
            for (int i = threadIdx.x; i < NN; i += 256) {
                int l = i ^ j;
                if (l > i) {
                    unsigned a = skey[i], c = skey[l];
                    bool up = ((i & k) == 0);
                    if ((a > c) == up) { skey[i] = c; skey[l] = a; }
                }
            }
            __syncthreads();
        }
    }

    for (int i = threadIdx.x; i < NN; i += 256) {
        int si = (int)(skey[i] & 2047u);
        const float* p = src + (off + si) * 3;
        float x = p[0], y = p[1], z = p[2];
        dst[off + i] = make_float4(x, y, z, (x * x + y * y + z * z) * S2F);
        pot[off + i] = 0.f;
    }
}

// ---------------------------------------------------------------------------
#define MERGEROW(m, s, off)                                         \
    {                                                               \
        float mo = __shfl_xor_sync(0xffffffffu, m, off);            \
        float so = __shfl_xor_sync(0xffffffffu, s, off);            \
        float mn = fmaxf(m, mo);                                    \
        s = fmaf(so, ex2f_(mo - mn), s * ex2f_(m - mn));            \
        m = mn;                                                     \
    }

#define ROWUPD(m, s, mt, a, e)                                      \
    if (__any_sync(0xffffffffu, (e) > 0.f)) {                       \
        if (__any_sync(0xffffffffu, (a) > (m))) {                   \
            float c = fmaxf(m, a);                                  \
            c = fmaxf(c, __shfl_xor_sync(0xffffffffu, c, 16));      \
            c = fmaxf(c, __shfl_xor_sync(0xffffffffu, c, 8));       \
            c = fmaxf(c, __shfl_xor_sync(0xffffffffu, c, 4));       \
            c = fmaxf(c, __shfl_xor_sync(0xffffffffu, c, 2));       \
            c = fmaxf(c, __shfl_xor_sync(0xffffffffu, c, 1));       \
            s = fmaf(s, ex2f_(m - c), ex2f_((a) - c));              \
            m = c; mt = c - TT;                                     \
        } else {                                                    \
            s += ex2f_((a) - m);                                    \
        }                                                           \
    }

// Boot half-update (iteration 0): full online LSE, stores exact row max.
__global__ void __launch_bounds__(256) half_boot(int dir) {
    int blk = blockIdx.x;
    int b = blk >> 6;
    int chunk = blk & 63;

    const float4* R4  = dir ? d_Q4 : d_P4;
    const float4* D4  = dir ? d_P4 : d_Q4;
    const float*  pin = dir ? d_f  : d_g;
    float*        pout = dir ? d_g : d_f;
    float*        mout = dir ? d_mg : d_mf;

    __shared__ float4 tbl[NN];
    {
        const float4* Db = D4 + b * NN;
        const float*  pb = pin + b * NN;
        for (int j = threadIdx.x; j < NN; j += 256) {
            float4 q = Db[j];
            float4 t;
            t.x = q.x * S2X2;
            t.y = q.y * S2X2;
            t.z = q.z * S2X2;
            t.w = fmaf(pb[j], S2F, -q.w);
            tbl[j] = t;
        }
    }
    __syncthreads();

    int warp = threadIdx.x >> 5;
    int lane = threadIdx.x & 31;
    int row0 = b * NN + chunk * 32 + warp * 4;

    float4 r0 = R4[row0 + 0];
    float4 r1 = R4[row0 + 1];
    float4 r2 = R4[row0 + 2];
    float4 r3 = R4[row0 + 3];

    const float NEGINF = -CUDART_INF_F;
    float m0 = NEGINF, m1 = NEGINF, m2 = NEGINF, m3 = NEGINF;
    float s0 = 0.f, s1 = 0.f, s2 = 0.f, s3 = 0.f;
    float mt0 = NEGINF, mt1 = NEGINF, mt2 = NEGINF, mt3 = NEGINF;

#pragma unroll 2
    for (int k = 0; k < 64; ++k) {
        float4 q = tbl[(k << 5) + lane];
        float a0 = fmaf(r0.x, q.x, fmaf(r0.y, q.y, fmaf(r0.z, q.z, q.w)));
        float a1 = fmaf(r1.x, q.x, fmaf(r1.y, q.y, fmaf(r1.z, q.z, q.w)));
        float a2 = fmaf(r2.x, q.x, fmaf(r2.y, q.y, fmaf(r2.z, q.z, q.w)));
        float a3 = fmaf(r3.x, q.x, fmaf(r3.y, q.y, fmaf(r3.z, q.z, q.w)));
        float e0 = a0 - mt0;
        float e1 = a1 - mt1;
        float e2 = a2 - mt2;
        float e3 = a3 - mt3;
        float emax = fmaxf(fmaxf(e0, e1), fmaxf(e2, e3));
        if (__any_sync(0xffffffffu, emax > 0.f)) {
            ROWUPD(m0, s0, mt0, a0, e0)
            ROWUPD(m1, s1, mt1, a1, e1)
            ROWUPD(m2, s2, mt2, a2, e2)
            ROWUPD(m3, s3, mt3, a3, e3)
        }
    }

#pragma unroll
    for (int o = 16; o; o >>= 1) {
        MERGEROW(m0, s0, o);
        MERGEROW(m1, s1, o);
        MERGEROW(m2, s2, o);
        MERGEROW(m3, s3, o);
    }

    if (lane == 0) {
        pout[row0 + 0] = fmaf(-EPSLN2, (-r0.w) + m0 + lg2f_(s0), EPSLOGMU);
        pout[row0 + 1] = fmaf(-EPSLN2, (-r1.w) + m1 + lg2f_(s1), EPSLOGMU);
        pout[row0 + 2] = fmaf(-EPSLN2, (-r2.w) + m2 + lg2f_(s2), EPSLOGMU);
        pout[row0 + 3] = fmaf(-EPSLN2, (-r3.w) + m3 + lg2f_(s3), EPSLOGMU);
        mout[row0 + 0] = m0;
        mout[row0 + 1] = m1;
        mout[row0 + 2] = m2;
        mout[row0 + 3] = m3;
    }
}

// ---------------------------------------------------------------------------
// Fast half-update: grid 1024 (16 rows/block, 2 rows/thread), branch-free.
__global__ void __launch_bounds__(256) half_fast(int dir) {
    int blk = blockIdx.x;
    int b = blk >> 7;          // 128 row-groups of 16 per batch
    int c16 = blk & 127;

    const float4* R4  = dir ? d_Q4 : d_P4;
    const float4* D4  = dir ? d_P4 : d_Q4;
    const float*  pin = dir ? d_f  : d_g;
    float*        pout = dir ? d_g : d_f;
    float*        marr = dir ? d_mg : d_mf;

    __shared__ float4 tbl[NN];
    {
        const float4* Db = D4 + b * NN;
        const float*  pb = pin + b * NN;
        for (int j = threadIdx.x; j < NN; j += 256) {
            float4 q = Db[j];
            float4 t;
            t.x = q.x * S2X2;
            t.y = q.y * S2X2;
            t.z = q.z * S2X2;
            t.w = fmaf(pb[j], S2F, -q.w);
            tbl[j] = t;
        }
    }
    __syncthreads();

    int warp = threadIdx.x >> 5;
    int lane = threadIdx.x & 31;
    int row0 = b * NN + c16 * 16 + warp * 2;

    float4 r0 = R4[row0 + 0];
    float4 r1 = R4[row0 + 1];

    float muT0 = marr[row0 + 0] - SLACKTT;
    float muT1 = marr[row0 + 1] - SLACKTT;

    float s0 = 0.f, s1 = 0.f;

#pragma unroll 16
    for (int k = 0; k < 64; ++k) {
        float4 q = tbl[(k << 5) + lane];
        float a0 = fmaf(r0.x, q.x, fmaf(r0.y, q.y, fmaf(r0.z, q.z, q.w)));
        float a1 = fmaf(r1.x, q.x, fmaf(r1.y, q.y, fmaf(r1.z, q.z, q.w)));
        s0 += ex2f_(a0 - muT0);   // underflow implements truncation
        s1 += ex2f_(a1 - muT1);
    }

#pragma unroll
    for (int o = 16; o; o >>= 1) {
        s0 += __shfl_xor_sync(0xffffffffu, s0, o);
        s1 += __shfl_xor_sync(0xffffffffu, s1, o);
    }

    if (lane == 0) {
        float l0 = lg2f_(s0);
        float l1 = lg2f_(s1);
        pout[row0 + 0] = fmaf(-EPSLN2, (-r0.w) + muT0 + l0, EPSLOGMU);
        pout[row0 + 1] = fmaf(-EPSLN2, (-r1.w) + muT1 + l1, EPSLOGMU);
        // carried row-max upper bound: muT + log2(s) >= true max
        marr[row0 + 0] = muT0 + l0;
        marr[row0 + 1] = muT1 + l1;
    }
}

// ---------------------------------------------------------------------------
// Loss: grid 1024, 2 rows/thread, branch-free.
__global__ void __launch_bounds__(256) loss_kernel() {
    int blk = blockIdx.x;
    int b = blk >> 7;
    int c16 = blk & 127;

    __shared__ float4 tbl[NN];
    __shared__ float  gg[NN];
    {
        const float4* Db = d_Q4 + b * NN;
        const float*  pb = d_g + b * NN;
        for (int j = threadIdx.x; j < NN; j += 256) {
            float4 q = Db[j];
            float gj = pb[j];
            float4 t;
            t.x = q.x * S2X2;
            t.y = q.y * S2X2;
            t.z = q.z * S2X2;
            t.w = fmaf(gj, S2F, -q.w);
            tbl[j] = t;
            gg[j] = gj;
        }
    }
    __syncthreads();

    int warp = threadIdx.x >> 5;
    int lane = threadIdx.x & 31;
    int row0 = b * NN + c16 * 16 + warp * 2;

    float4 r0 = d_P4[row0 + 0];
    float4 r1 = d_P4[row0 + 1];
    float fr0 = d_f[row0 + 0], fr1 = d_f[row0 + 1];
    float ff0 = fmaf(fr0, S2F, -r0.w);
    float ff1 = fmaf(fr1, S2F, -r1.w);

    float part = 0.f;
#pragma unroll 8
    for (int k = 0; k < 64; ++k) {
        int j = (k << 5) + lane;
        float4 q = tbl[j];
        float gj = gg[j];
        {
            float a = fmaf(r0.x, q.x, fmaf(r0.y, q.y, fmaf(r0.z, q.z, q.w)));
            float arg = a + ff0;
            float C = fmaf(-EPSLN2, arg, fr0 + gj);
            part = fmaf(ex2f_(arg), C, part);
        }
        {
            float a = fmaf(r1.x, q.x, fmaf(r1.y, q.y, fmaf(r1.z, q.z, q.w)));
            float arg = a + ff1;
            float C = fmaf(-EPSLN2, arg, fr1 + gj);
            part = fmaf(ex2f_(arg), C, part);
        }
    }

    __shared__ float red[256];
    red[threadIdx.x] = part;
    __syncthreads();
#pragma unroll
    for (int o = 128; o; o >>= 1) {
        if (threadIdx.x < o) red[threadIdx.x] += red[threadIdx.x + o];
        __syncthreads();
    }
    if (threadIdx.x == 0) d_partials[blockIdx.x] = red[0];
}

__global__ void reduce_kernel(float* __restrict__ out) {
    __shared__ float red[256];
    float v = 0.f;
    for (int i = threadIdx.x; i < 1024; i += 256) v += d_partials[i];
    red[threadIdx.x] = v;
    __syncthreads();
#pragma unroll
    for (int o = 128; o; o >>= 1) {
        if (threadIdx.x < o) red[threadIdx.x] += red[threadIdx.x + o];
        __syncthreads();
    }
    if (threadIdx.x == 0) out[0] = red[0] * 0.125f;
}

extern "C" void kernel_launch(void* const* d_in, const int* in_sizes, int n_in,
                              void* d_out, int out_size) {
    const float* preds = (const float*)d_in[0];
    const float* gts   = (const float*)d_in[1];
    float* out = (float*)d_out;

    prep_sort_kernel<<<BB * 2, 256>>>(preds, gts);
    half_boot<<<BB * 64, 256>>>(0);
    half_boot<<<BB * 64, 256>>>(1);
    for (int it = 1; it < 50; ++it) {
        half_fast<<<BB * 128, 256>>>(0);
        half_fast<<<BB * 128, 256>>>(1);
    }
    loss_kernel<<<BB * 128, 256>>>();
    reduce_kernel<<<1, 256>>>(out);
}

// round 10
// speedup vs baseline: 1.2300x; 1.0929x over previous
#include <cuda_runtime.h>
#include <math_constants.h>

// EMDLoss (Sinkhorn, eps=0.005, 50 iters), B=8, N=2048, dim=3.
// Morton-sorted sets; log2-domain factored cost. State per row = per-half
// truncated lse L[half][row] (a-units). Fast iterations: branch-free
// s += ex2(a - muT), muT = max(L0,L1) - SLACKTT; L_half = muT + lg2(s).
// 4 rows/thread (one LDS.128 serves 4 rows), j-half split for grid 1024.

#define BB 8
#define NN 2048
#define LOG2N 11.0f

static __device__ float4 d_P4[BB * NN];   // sorted (x,y,z, |p|^2*S2)
static __device__ float4 d_Q4[BB * NN];
static __device__ float  d_LP[2][BB * NN];  // per-half truncated lse (a-units)
static __device__ float  d_LQ[2][BB * NN];
static __device__ float  d_partials[1024];

__device__ __forceinline__ float ex2f_(float x) {
    float r; asm("ex2.approx.f32 %0, %1;" : "=f"(r) : "f"(x)); return r;
}
__device__ __forceinline__ float lg2f_(float x) {
    float r; asm("lg2.approx.f32 %0, %1;" : "=f"(r) : "f"(x)); return r;
}
// combine two half-lse values (log2 domain)
__device__ __forceinline__ float comb2_(float L0, float L1) {
    float m = fmaxf(L0, L1);
    float n = fminf(L0, L1);
    return m + lg2f_(1.f + ex2f_(n - m));
}

#define S2F      288.5390081777927f      // 1/(eps*ln2)
#define S2X2     577.0780163555854f      // 2/(eps*ln2)
#define EPSLN2   0.0034657359027997f     // eps*ln2
#define EPSLOGMU (-0.03812309493079699f) // eps * (-ln N)
#define TT       25.0f
#define SLACKTT  44.0f                   // TT + window-pop bound (11) + drift

// ---------------------------------------------------------------------------
__global__ void __launch_bounds__(256) prep_sort_kernel(
    const float* __restrict__ preds, const float* __restrict__ gts) {
    int blk = blockIdx.x;
    int b = blk >> 1;
    int set = blk & 1;
    const float* src = set ? gts : preds;
    float4* dst = set ? d_Q4 : d_P4;
    int off = b * NN;

    __shared__ unsigned skey[NN];

    for (int i = threadIdx.x; i < NN; i += 256) {
        const float* p = src + (off + i) * 3;
        float x = p[0], y = p[1], z = p[2];
        int ux = (int)floorf((x + 4.f) * 4.f); ux = min(31, max(0, ux));
        int uy = (int)floorf((y + 4.f) * 4.f); uy = min(31, max(0, uy));
        int uz = (int)floorf((z + 4.f) * 4.f); uz = min(31, max(0, uz));
        unsigned key = 0;
#pragma unroll
        for (int bit = 0; bit < 5; ++bit) {
            key |= (((unsigned)ux >> bit) & 1u) << (3 * bit + 2);
            key |= (((unsigned)uy >> bit) & 1u) << (3 * bit + 1);
            key |= (((unsigned)uz >> bit) & 1u) << (3 * bit + 0);
        }
        skey[i] = (key << 11) | (unsigned)i;
    }
    __syncthreads();

    for (int k = 2; k <= NN; k <<= 1) {
        for (int j = k >> 1; j > 0; j >>= 1) {
            for (int i = threadIdx.x; i < NN; i += 256) {
                int l = i ^ j;
                if (l > i) {
                    unsigned a = skey[i], c = skey[l];
                    bool up = ((i & k) == 0);
                    if ((a > c) == up) { skey[i] = c; skey[l] = a; }
                }
            }
            __syncthreads();
        }
    }

    for (int i = threadIdx.x; i < NN; i += 256) {
        int si = (int)(skey[i] & 2047u);
        const float* p = src + (off + si) * 3;
        float x = p[0], y = p[1], z = p[2];
        dst[off + i] = make_float4(x, y, z, (x * x + y * y + z * z) * S2F);
    }
}

// ---------------------------------------------------------------------------
// Common decode: grid = BB * 64 rowgroups * 2 j-halves.
#define DECODE_BLK()                                                \
    int blk = blockIdx.x;                                           \
    int b = blk >> 7;                                               \
    int rest = blk & 127;                                           \
    int rg = rest >> 1;                                             \
    int half = rest & 1;                                            \
    int off = b * NN;

#define MERGEROW(m, s, off)                                         \
    {                                                               \
        float mo = __shfl_xor_sync(0xffffffffu, m, off);            \
        float so = __shfl_xor_sync(0xffffffffu, s, off);            \
        float mn = fmaxf(m, mo);                                    \
        s = fmaf(so, ex2f_(mo - mn), s * ex2f_(m - mn));            \
        m = mn;                                                     \
    }

#define ROWUPD(m, s, mt, a, e)                                      \
    if (__any_sync(0xffffffffu, (e) > 0.f)) {                       \
        if (__any_sync(0xffffffffu, (a) > (m))) {                   \
            float c = fmaxf(m, a);                                  \
            c = fmaxf(c, __shfl_xor_sync(0xffffffffu, c, 16));      \
            c = fmaxf(c, __shfl_xor_sync(0xffffffffu, c, 8));       \
            c = fmaxf(c, __shfl_xor_sync(0xffffffffu, c, 4));       \
            c = fmaxf(c, __shfl_xor_sync(0xffffffffu, c, 2));       \
            c = fmaxf(c, __shfl_xor_sync(0xffffffffu, c, 1));       \
            s = fmaf(s, ex2f_(m - c), ex2f_((a) - c));              \
            m = c; mt = c - TT;                                     \
        } else {                                                    \
            s += ex2f_((a) - m);                                    \
        }                                                           \
    }

// Boot half-update (iteration 0): online LSE over this j-half; stores L.
// dir=0: rows=P, table=Q with pot=0. dir=1: rows=Q, table=P via d_LP.
__global__ void __launch_bounds__(256) half_boot(int dir) {
    DECODE_BLK();

    const float4* R4 = dir ? d_Q4 : d_P4;
    const float4* D4 = dir ? d_P4 : d_Q4;
    float* rL = dir ? d_LQ[half] : d_LP[half];

    __shared__ float4 tbl[NN / 2];
    for (int t = threadIdx.x; t < NN / 2; t += 256) {
        int j = off + (half << 10) + t;
        float4 q = D4[j];
        float4 tt;
        tt.x = q.x * S2X2;
        tt.y = q.y * S2X2;
        tt.z = q.z * S2X2;
        tt.w = dir ? (-LOG2N - comb2_(d_LP[0][j], d_LP[1][j])) : -q.w;
        tbl[t] = tt;
    }
    __syncthreads();

    int warp = threadIdx.x >> 5;
    int lane = threadIdx.x & 31;
    int row0 = off + rg * 32 + warp * 4;

    float4 r0 = R4[row0 + 0];
    float4 r1 = R4[row0 + 1];
    float4 r2 = R4[row0 + 2];
    float4 r3 = R4[row0 + 3];

    const float NEGINF = -CUDART_INF_F;
    float m0 = NEGINF, m1 = NEGINF, m2 = NEGINF, m3 = NEGINF;
    float s0 = 0.f, s1 = 0.f, s2 = 0.f, s3 = 0.f;
    float mt0 = NEGINF, mt1 = NEGINF, mt2 = NEGINF, mt3 = NEGINF;

#pragma unroll 2
    for (int k = 0; k < 32; ++k) {
        float4 q = tbl[(k << 5) + lane];
        float a0 = fmaf(r0.x, q.x, fmaf(r0.y, q.y, fmaf(r0.z, q.z, q.w)));
        float a1 = fmaf(r1.x, q.x, fmaf(r1.y, q.y, fmaf(r1.z, q.z, q.w)));
        float a2 = fmaf(r2.x, q.x, fmaf(r2.y, q.y, fmaf(r2.z, q.z, q.w)));
        float a3 = fmaf(r3.x, q.x, fmaf(r3.y, q.y, fmaf(r3.z, q.z, q.w)));
        float e0 = a0 - mt0;
        float e1 = a1 - mt1;
        float e2 = a2 - mt2;
        float e3 = a3 - mt3;
        float emax = fmaxf(fmaxf(e0, e1), fmaxf(e2, e3));
        if (__any_sync(0xffffffffu, emax > 0.f)) {
            ROWUPD(m0, s0, mt0, a0, e0)
            ROWUPD(m1, s1, mt1, a1, e1)
            ROWUPD(m2, s2, mt2, a2, e2)
            ROWUPD(m3, s3, mt3, a3, e3)
        }
    }

#pragma unroll
    for (int o = 16; o; o >>= 1) {
        MERGEROW(m0, s0, o);
        MERGEROW(m1, s1, o);
        MERGEROW(m2, s2, o);
        MERGEROW(m3, s3, o);
    }

    if (lane == 0) {
        rL[row0 + 0] = m0 + lg2f_(s0);
        rL[row0 + 1] = m1 + lg2f_(s1);
        rL[row0 + 2] = m2 + lg2f_(s2);
        rL[row0 + 3] = m3 + lg2f_(s3);
    }
}

// ---------------------------------------------------------------------------
// Fast half-update: 4 rows/thread, branch-free, j-half table.
__global__ void __launch_bounds__(256) half_fast(int dir) {
    DECODE_BLK();

    const float4* R4 = dir ? d_Q4 : d_P4;
    const float4* D4 = dir ? d_P4 : d_Q4;
    const float* tL0 = dir ? d_LP[0] : d_LQ[0];
    const float* tL1 = dir ? d_LP[1] : d_LQ[1];
    const float* rLA = dir ? d_LQ[0] : d_LP[0];
    const float* rLB = dir ? d_LQ[1] : d_LP[1];
    float* rL = dir ? d_LQ[half] : d_LP[half];

    __shared__ float4 tbl[NN / 2];
    for (int t = threadIdx.x; t < NN / 2; t += 256) {
        int j = off + (half << 10) + t;
        float4 q = D4[j];
        float4 tt;
        tt.x = q.x * S2X2;
        tt.y = q.y * S2X2;
        tt.z = q.z * S2X2;
        tt.w = -LOG2N - comb2_(tL0[j], tL1[j]);   // pot*S2 - qq*S2
        tbl[t] = tt;
    }
    __syncthreads();

    int warp = threadIdx.x >> 5;
    int lane = threadIdx.x & 31;
    int row0 = off + rg * 32 + warp * 4;

    float4 r0 = R4[row0 + 0];
    float4 r1 = R4[row0 + 1];
    float4 r2 = R4[row0 + 2];
    float4 r3 = R4[row0 + 3];

    float muT0 = fmaxf(rLA[row0 + 0], rLB[row0 + 0]) - SLACKTT;
    float muT1 = fmaxf(rLA[row0 + 1], rLB[row0 + 1]) - SLACKTT;
    float muT2 = fmaxf(rLA[row0 + 2], rLB[row0 + 2]) - SLACKTT;
    float muT3 = fmaxf(rLA[row0 + 3], rLB[row0 + 3]) - SLACKTT;

    float s0 = 0.f, s1 = 0.f, s2 = 0.f, s3 = 0.f;

#pragma unroll 8
    for (int k = 0; k < 32; ++k) {
        float4 q = tbl[(k << 5) + lane];
        float a0 = fmaf(r0.x, q.x, fmaf(r0.y, q.y, fmaf(r0.z, q.z, q.w)));
        float a1 = fmaf(r1.x, q.x, fmaf(r1.y, q.y, fmaf(r1.z, q.z, q.w)));
        float a2 = fmaf(r2.x, q.x, fmaf(r2.y, q.y, fmaf(r2.z, q.z, q.w)));
        float a3 = fmaf(r3.x, q.x, fmaf(r3.y, q.y, fmaf(r3.z, q.z, q.w)));
        s0 += ex2f_(a0 - muT0);   // underflow = truncation
        s1 += ex2f_(a1 - muT1);
        s2 += ex2f_(a2 - muT2);
        s3 += ex2f_(a3 - muT3);
    }

#pragma unroll
    for (int o = 16; o; o >>= 1) {
        s0 += __shfl_xor_sync(0xffffffffu, s0, o);
        s1 += __shfl_xor_sync(0xffffffffu, s1, o);
        s2 += __shfl_xor_sync(0xffffffffu, s2, o);
        s3 += __shfl_xor_sync(0xffffffffu, s3, o);
    }

    if (lane == 0) {
        rL[row0 + 0] = muT0 + lg2f_(s0);   // exact truncated half-lse
        rL[row0 + 1] = muT1 + lg2f_(s1);
        rL[row0 + 2] = muT2 + lg2f_(s2);
        rL[row0 + 3] = muT3 + lg2f_(s3);
    }
}

// ---------------------------------------------------------------------------
// Loss: 4 rows/thread, branch-free; reconstruct f and g from L arrays.
__global__ void __launch_bounds__(256) loss_kernel() {
    DECODE_BLK();

    __shared__ float4 tbl[NN / 2];
    __shared__ float  gg[NN / 2];
    for (int t = threadIdx.x; t < NN / 2; t += 256) {
        int j = off + (half << 10) + t;
        float4 q = d_Q4[j];
        float lse = comb2_(d_LQ[0][j], d_LQ[1][j]);
        float4 tt;
        tt.x = q.x * S2X2;
        tt.y = q.y * S2X2;
        tt.z = q.z * S2X2;
        tt.w = -LOG2N - lse;
        tbl[t] = tt;
        gg[t] = fmaf(-EPSLN2, lse - q.w, EPSLOGMU);   // g_j
    }
    __syncthreads();

    int warp = threadIdx.x >> 5;
    int lane = threadIdx.x & 31;
    int row0 = off + rg * 32 + warp * 4;

    float4 r0 = d_P4[row0 + 0];
    float4 r1 = d_P4[row0 + 1];
    float4 r2 = d_P4[row0 + 2];
    float4 r3 = d_P4[row0 + 3];

    float lf0 = comb2_(d_LP[0][row0 + 0], d_LP[1][row0 + 0]);
    float lf1 = comb2_(d_LP[0][row0 + 1], d_LP[1][row0 + 1]);
    float lf2 = comb2_(d_LP[0][row0 + 2], d_LP[1][row0 + 2]);
    float lf3 = comb2_(d_LP[0][row0 + 3], d_LP[1][row0 + 3]);

    float fr0 = fmaf(-EPSLN2, lf0 - r0.w, EPSLOGMU);
    float fr1 = fmaf(-EPSLN2, lf1 - r1.w, EPSLOGMU);
    float fr2 = fmaf(-EPSLN2, lf2 - r2.w, EPSLOGMU);
    float fr3 = fmaf(-EPSLN2, lf3 - r3.w, EPSLOGMU);

    float ff0 = -LOG2N - lf0;   // f*S2 - pp*S2
    float ff1 = -LOG2N - lf1;
    float ff2 = -LOG2N - lf2;
    float ff3 = -LOG2N - lf3;

    float part = 0.f;
#pragma unroll 4
    for (int k = 0; k < 32; ++k) {
        int j = (k << 5) + lane;
        float4 q = tbl[j];
        float gj = gg[j];
        {
            float a = fmaf(r0.x, q.x, fmaf(r0.y, q.y, fmaf(r0.z, q.z, q.w)));
            float arg = a + ff0;
            float C = fmaf(-EPSLN2, arg, fr0 + gj);
            part = fmaf(ex2f_(arg), C, part);
        }
        {
            float a = fmaf(r1.x, q.x, fmaf(r1.y, q.y, fmaf(r1.z, q.z, q.w)));
            float arg = a + ff1;
            float C = fmaf(-EPSLN2, arg, fr1 + gj);
            part = fmaf(ex2f_(arg), C, part);
        }
        {
            float a = fmaf(r2.x, q.x, fmaf(r2.y, q.y, fmaf(r2.z, q.z, q.w)));
            float arg = a + ff2;
            float C = fmaf(-EPSLN2, arg, fr2 + gj);
            part = fmaf(ex2f_(arg), C, part);
        }
        {
            float a = fmaf(r3.x, q.x, fmaf(r3.y, q.y, fmaf(r3.z, q.z, q.w)));
            float arg = a + ff3;
            float C = fmaf(-EPSLN2, arg, fr3 + gj);
            part = fmaf(ex2f_(arg), C, part);
        }
    }

    __shared__ float red[256];
    red[threadIdx.x] = part;
    __syncthreads();
#pragma unroll
    for (int o = 128; o; o >>= 1) {
        if (threadIdx.x < o) red[threadIdx.x] += red[threadIdx.x + o];
        __syncthreads();
    }
    if (threadIdx.x == 0) d_partials[blockIdx.x] = red[0];
}

__global__ void reduce_kernel(float* __restrict__ out) {
    __shared__ float red[256];
    float v = 0.f;
    for (int i = threadIdx.x; i < 1024; i += 256) v += d_partials[i];
    red[threadIdx.x] = v;
    __syncthreads();
#pragma unroll
    for (int o = 128; o; o >>= 1) {
        if (threadIdx.x < o) red[threadIdx.x] += red[threadIdx.x + o];
        __syncthreads();
    }
    if (threadIdx.x == 0) out[0] = red[0] * 0.125f;
}

extern "C" void kernel_launch(void* const* d_in, const int* in_sizes, int n_in,
                              void* d_out, int out_size) {
    const float* preds = (const float*)d_in[0];
    const float* gts   = (const float*)d_in[1];
    float* out = (float*)d_out;

    prep_sort_kernel<<<BB * 2, 256>>>(preds, gts);
    half_boot<<<BB * 128, 256>>>(0);
    half_boot<<<BB * 128, 256>>>(1);
    for (int it = 1; it < 50; ++it) {
        half_fast<<<BB * 128, 256>>>(0);
        half_fast<<<BB * 128, 256>>>(1);
    }
    loss_kernel<<<BB * 128, 256>>>();
    reduce_kernel<<<1, 256>>>(out);
}

// round 12
// speedup vs baseline: 1.2431x; 1.0106x over previous
#include <cuda_runtime.h>
#include <cuda_fp16.h>
#include <math_constants.h>

// EMDLoss (Sinkhorn, eps=0.005, 50 iters), B=8, N=2048, dim=3.
// Morton-sorted sets; log2-domain factored cost. State per row = per-half
// truncated lse L[half][row]. Fast iterations: PER-ROW anchor muT_i =
// prev lse (max term ~2^0 always survives -> no fp16 underflow collapse),
// ex2.approx.f16x2 (2 exps per MUFU op), clamp +12, fp32 flush every 8.

#define BB 8
#define NN 2048
#define LOG2N 11.0f

static __device__ float4 d_P4[BB * NN];     // sorted (x,y,z, |p|^2*S2)
static __device__ float4 d_Q4[BB * NN];
static __device__ float  d_LP[2][BB * NN];  // per-half truncated lse (a-units)
static __device__ float  d_LQ[2][BB * NN];
static __device__ float  d_partials[1024];

__device__ __forceinline__ float ex2f_(float x) {
    float r; asm("ex2.approx.f32 %0, %1;" : "=f"(r) : "f"(x)); return r;
}
__device__ __forceinline__ float lg2f_(float x) {
    float r; asm("lg2.approx.f32 %0, %1;" : "=f"(r) : "f"(x)); return r;
}
// combine two half-lse values (log2 domain).
__device__ __forceinline__ float comb2_(float L0, float L1) {
    float m = fmaxf(L0, L1);
    float n = fminf(L0, L1);
    return m + lg2f_(1.f + ex2f_(n - m));
}

#define S2F      288.5390081777927f      // 1/(eps*ln2)
#define S2X2     577.0780163555854f      // 2/(eps*ln2)
#define EPSLN2   0.0034657359027997f     // eps*ln2
#define EPSLOGMU (-0.03812309493079699f) // eps * (-ln N)
#define TT       25.0f

// ---------------------------------------------------------------------------
__global__ void __launch_bounds__(256) prep_sort_kernel(
    const float* __restrict__ preds, const float* __restrict__ gts) {
    int blk = blockIdx.x;
    int b = blk >> 1;
    int set = blk & 1;
    const float* src = set ? gts : preds;
    float4* dst = set ? d_Q4 : d_P4;
    int off = b * NN;

    __shared__ unsigned skey[NN];

    for (int i = threadIdx.x; i < NN; i += 256) {
        const float* p = src + (off + i) * 3;
        float x = p[0], y = p[1], z = p[2];
        int ux = (int)floorf((x + 4.f) * 4.f); ux = min(31, max(0, ux));
        int uy = (int)floorf((y + 4.f) * 4.f); uy = min(31, max(0, uy));
        int uz = (int)floorf((z + 4.f) * 4.f); uz = min(31, max(0, uz));
        unsigned key = 0;
#pragma unroll
        for (int bit = 0; bit < 5; ++bit) {
            key |= (((unsigned)ux >> bit) & 1u) << (3 * bit + 2);
            key |= (((unsigned)uy >> bit) & 1u) << (3 * bit + 1);
            key |= (((unsigned)uz >> bit) & 1u) << (3 * bit + 0);
        }
        skey[i] = (key << 11) | (unsigned)i;
    }
    __syncthreads();

    for (int k = 2; k <= NN; k <<= 1) {
        for (int j = k >> 1; j > 0; j >>= 1) {
            for (int i = threadIdx.x; i < NN; i += 256) {
                int l = i ^ j;
                if (l > i) {
                    unsigned a = skey[i], c = skey[l];
                    bool up = ((i & k) == 0);
                    if ((a > c) == up) { skey[i] = c; skey[l] = a; }
                }
            }
            __syncthreads();
        }
    }

    for (int i = threadIdx.x; i < NN; i += 256) {
        int si = (int)(skey[i] & 2047u);
        const float* p = src + (off + si) * 3;
        float x = p[0], y = p[1], z = p[2];
        dst[off + i] = make_float4(x, y, z, (x * x + y * y + z * z) * S2F);
    }
}

// ---------------------------------------------------------------------------
// Common decode: grid = BB * 64 rowgroups * 2 j-halves.
#define DECODE_BLK()                                                \
    int blk = blockIdx.x;                                           \
    int b = blk >> 7;                                               \
    int rest = blk & 127;                                           \
    int rg = rest >> 1;                                             \
    int half = rest & 1;                                            \
    int off = b * NN;

#define MERGEROW(m, s, off)                                         \
    {                                                               \
        float mo = __shfl_xor_sync(0xffffffffu, m, off);            \
        float so = __shfl_xor_sync(0xffffffffu, s, off);            \
        float mn = fmaxf(m, mo);                                    \
        s = fmaf(so, ex2f_(mo - mn), s * ex2f_(m - mn));            \
        m = mn;                                                     \
    }

#define ROWUPD(m, s, mt, a, e)                                      \
    if (__any_sync(0xffffffffu, (e) > 0.f)) {                       \
        if (__any_sync(0xffffffffu, (a) > (m))) {                   \
            float c = fmaxf(m, a);                                  \
            c = fmaxf(c, __shfl_xor_sync(0xffffffffu, c, 16));      \
            c = fmaxf(c, __shfl_xor_sync(0xffffffffu, c, 8));       \
            c = fmaxf(c, __shfl_xor_sync(0xffffffffu, c, 4));       \
            c = fmaxf(c, __shfl_xor_sync(0xffffffffu, c, 2));       \
            c = fmaxf(c, __shfl_xor_sync(0xffffffffu, c, 1));       \
            s = fmaf(s, ex2f_(m - c), ex2f_((a) - c));              \
            m = c; mt = c - TT;                                     \
        } else {                                                    \
            s += ex2f_((a) - m);                                    \
        }                                                           \
    }

// Boot half-update (iteration 0): fp32 online LSE over this j-half; stores L.
__global__ void __launch_bounds__(256) half_boot(int dir) {
    DECODE_BLK();

    const float4* R4 = dir ? d_Q4 : d_P4;
    const float4* D4 = dir ? d_P4 : d_Q4;
    float* rL = dir ? d_LQ[half] : d_LP[half];

    __shared__ float4 tbl[NN / 2];
    for (int t = threadIdx.x; t < NN / 2; t += 256) {
        int j = off + (half << 10) + t;
        float4 q = D4[j];
        float4 tt;
        tt.x = q.x * S2X2;
        tt.y = q.y * S2X2;
        tt.z = q.z * S2X2;
        tt.w = dir ? (-LOG2N - comb2_(d_LP[0][j], d_LP[1][j])) : -q.w;
        tbl[t] = tt;
    }
    __syncthreads();

    int warp = threadIdx.x >> 5;
    int lane = threadIdx.x & 31;
    int row0 = off + rg * 32 + warp * 4;

    float4 r0 = R4[row0 + 0];
    float4 r1 = R4[row0 + 1];
    float4 r2 = R4[row0 + 2];
    float4 r3 = R4[row0 + 3];

    const float NEGINF = -CUDART_INF_F;
    float m0 = NEGINF, m1 = NEGINF, m2 = NEGINF, m3 = NEGINF;
    float s0 = 0.f, s1 = 0.f, s2 = 0.f, s3 = 0.f;
    float mt0 = NEGINF, mt1 = NEGINF, mt2 = NEGINF, mt3 = NEGINF;

#pragma unroll 2
    for (int k = 0; k < 32; ++k) {
        float4 q = tbl[(k << 5) + lane];
        float a0 = fmaf(r0.x, q.x, fmaf(r0.y, q.y, fmaf(r0.z, q.z, q.w)));
        float a1 = fmaf(r1.x, q.x, fmaf(r1.y, q.y, fmaf(r1.z, q.z, q.w)));
        float a2 = fmaf(r2.x, q.x, fmaf(r2.y, q.y, fmaf(r2.z, q.z, q.w)));
        float a3 = fmaf(r3.x, q.x, fmaf(r3.y, q.y, fmaf(r3.z, q.z, q.w)));
        float e0 = a0 - mt0;
        float e1 = a1 - mt1;
        float e2 = a2 - mt2;
        float e3 = a3 - mt3;
        float emax = fmaxf(fmaxf(e0, e1), fmaxf(e2, e3));
        if (__any_sync(0xffffffffu, emax > 0.f)) {
            ROWUPD(m0, s0, mt0, a0, e0)
            ROWUPD(m1, s1, mt1, a1, e1)
            ROWUPD(m2, s2, mt2, a2, e2)
            ROWUPD(m3, s3, mt3, a3, e3)
        }
    }

#pragma unroll
    for (int o = 16; o; o >>= 1) {
        MERGEROW(m0, s0, o);
        MERGEROW(m1, s1, o);
        MERGEROW(m2, s2, o);
        MERGEROW(m3, s3, o);
    }

    if (lane == 0) {
        rL[row0 + 0] = m0 + lg2f_(s0);
        rL[row0 + 1] = m1 + lg2f_(s1);
        rL[row0 + 2] = m2 + lg2f_(s2);
        rL[row0 + 3] = m3 + lg2f_(s3);
    }
}

// ---------------------------------------------------------------------------
// Fast half-update: per-row anchor (muT_i = prev lse), fp16x2 exponentials.
__global__ void __launch_bounds__(256) half_fast(int dir) {
    DECODE_BLK();

    const float4* R4 = dir ? d_Q4 : d_P4;
    const float4* D4 = dir ? d_P4 : d_Q4;
    const float* tL0 = dir ? d_LP[0] : d_LQ[0];
    const float* tL1 = dir ? d_LP[1] : d_LQ[1];
    const float* rLA = dir ? d_LQ[0] : d_LP[0];
    const float* rLB = dir ? d_LQ[1] : d_LP[1];
    float* rL = dir ? d_LQ[half] : d_LP[half];

    __shared__ float4 tbl[NN / 2];
    for (int t = threadIdx.x; t < NN / 2; t += 256) {
        int j = off + (half << 10) + t;
        float4 q = D4[j];
        float4 tt;
        tt.x = q.x * S2X2;
        tt.y = q.y * S2X2;
        tt.z = q.z * S2X2;
        tt.w = -LOG2N - comb2_(tL0[j], tL1[j]);   // pot*S2 - qq*S2
        tbl[t] = tt;
    }
    __syncthreads();

    int warp = threadIdx.x >> 5;
    int lane = threadIdx.x & 31;
    int row0 = off + rg * 32 + warp * 4;

    float4 r0 = R4[row0 + 0];
    float4 r1 = R4[row0 + 1];
    float4 r2 = R4[row0 + 2];
    float4 r3 = R4[row0 + 3];

    // per-row anchor = previous full lse (max term ~ 2^0 always survives)
    float muT0 = fmaxf(rLA[row0 + 0], rLB[row0 + 0]);
    float muT1 = fmaxf(rLA[row0 + 1], rLB[row0 + 1]);
    float muT2 = fmaxf(rLA[row0 + 2], rLB[row0 + 2]);
    float muT3 = fmaxf(rLA[row0 + 3], rLB[row0 + 3]);

    const __half2 clampv = __float2half2_rn(12.f);
    float s0 = 1e-9f, s1 = 1e-9f, s2 = 1e-9f, s3 = 1e-9f;  // lg2(0) guard

#pragma unroll
    for (int kk = 0; kk < 4; ++kk) {
        __half2 acc01 = __float2half2_rn(0.f);
        __half2 acc23 = __float2half2_rn(0.f);
#pragma unroll
        for (int k2 = 0; k2 < 8; ++k2) {
            int k = (kk << 3) + k2;
            float4 q = tbl[(k << 5) + lane];
            float a0 = fmaf(r0.x, q.x, fmaf(r0.y, q.y, fmaf(r0.z, q.z, q.w)));
            float a1 = fmaf(r1.x, q.x, fmaf(r1.y, q.y, fmaf(r1.z, q.z, q.w)));
            float a2 = fmaf(r2.x, q.x, fmaf(r2.y, q.y, fmaf(r2.z, q.z, q.w)));
            float a3 = fmaf(r3.x, q.x, fmaf(r3.y, q.y, fmaf(r3.z, q.z, q.w)));
            __half2 h01 = __hmin2(__floats2half2_rn(a0 - muT0, a1 - muT1), clampv);
            __half2 h23 = __hmin2(__floats2half2_rn(a2 - muT2, a3 - muT3), clampv);
            acc01 = __hadd2(acc01, h2exp2(h01));
            acc23 = __hadd2(acc23, h2exp2(h23));
        }
        float2 f01 = __half22float2(acc01);
        float2 f23 = __half22float2(acc23);
        s0 += f01.x; s1 += f01.y;
        s2 += f23.x; s3 += f23.y;
    }

#pragma unroll
    for (int o = 16; o; o >>= 1) {
        s0 += __shfl_xor_sync(0xffffffffu, s0, o);
        s1 += __shfl_xor_sync(0xffffffffu, s1, o);
        s2 += __shfl_xor_sync(0xffffffffu, s2, o);
        s3 += __shfl_xor_sync(0xffffffffu, s3, o);
    }

    if (lane == 0) {
        rL[row0 + 0] = muT0 + lg2f_(s0);   // truncated half-lse
        rL[row0 + 1] = muT1 + lg2f_(s1);
        rL[row0 + 2] = muT2 + lg2f_(s2);
        rL[row0 + 3] = muT3 + lg2f_(s3);
    }
}

// ---------------------------------------------------------------------------
// Loss: 4 rows/thread, branch-free fp32; reconstruct f and g from L arrays.
__global__ void __launch_bounds__(256) loss_kernel() {
    DECODE_BLK();

    __shared__ float4 tbl[NN / 2];
    __shared__ float  gg[NN / 2];
    for (int t = threadIdx.x; t < NN / 2; t += 256) {
        int j = off + (half << 10) + t;
        float4 q = d_Q4[j];
        float lse = comb2_(d_LQ[0][j], d_LQ[1][j]);
        float4 tt;
        tt.x = q.x * S2X2;
        tt.y = q.y * S2X2;
        tt.z = q.z * S2X2;
        tt.w = -LOG2N - lse;
        tbl[t] = tt;
        gg[t] = fmaf(-EPSLN2, lse - q.w, EPSLOGMU);   // g_j
    }
    __syncthreads();

    int warp = threadIdx.x >> 5;
    int lane = threadIdx.x & 31;
    int row0 = off + rg * 32 + warp * 4;

    float4 r0 = d_P4[row0 + 0];
    float4 r1 = d_P4[row0 + 1];
    float4 r2 = d_P4[row0 + 2];
    float4 r3 = d_P4[row0 + 3];

    float lf0 = comb2_(d_LP[0][row0 + 0], d_LP[1][row0 + 0]);
    float lf1 = comb2_(d_LP[0][row0 + 1], d_LP[1][row0 + 1]);
    float lf2 = comb2_(d_LP[0][row0 + 2], d_LP[1][row0 + 2]);
    float lf3 = comb2_(d_LP[0][row0 + 3], d_LP[1][row0 + 3]);

    float fr0 = fmaf(-EPSLN2, lf0 - r0.w, EPSLOGMU);
    float fr1 = fmaf(-EPSLN2, lf1 - r1.w, EPSLOGMU);
    float fr2 = fmaf(-EPSLN2, lf2 - r2.w, EPSLOGMU);
    float fr3 = fmaf(-EPSLN2, lf3 - r3.w, EPSLOGMU);

    float ff0 = -LOG2N - lf0;   // f*S2 - pp*S2
    float ff1 = -LOG2N - lf1;
    float ff2 = -LOG2N - lf2;
    float ff3 = -LOG2N - lf3;

    float part = 0.f;
#pragma unroll 4
    for (int k = 0; k < 32; ++k) {
        int j = (k << 5) + lane;
        float4 q = tbl[j];
        float gj = gg[j];
        {
            float a = fmaf(r0.x, q.x, fmaf(r0.y, q.y, fmaf(r0.z, q.z, q.w)));
            float arg = a + ff0;
            float C = fmaf(-EPSLN2, arg, fr0 + gj);
            part = fmaf(ex2f_(arg), C, part);
        }
        {
            float a = fmaf(r1.x, q.x, fmaf(r1.y, q.y, fmaf(r1.z, q.z, q.w)));
            float arg = a + ff1;
            float C = fmaf(-EPSLN2, arg, fr1 + gj);
            part = fmaf(ex2f_(arg), C, part);
        }
        {
            float a = fmaf(r2.x, q.x, fmaf(r2.y, q.y, fmaf(r2.z, q.z, q.w)));
            float arg = a + ff2;
            float C = fmaf(-EPSLN2, arg, fr2 + gj);
            part = fmaf(ex2f_(arg), C, part);
        }
        {
            float a = fmaf(r3.x, q.x, fmaf(r3.y, q.y, fmaf(r3.z, q.z, q.w)));
            float arg = a + ff3;
            float C = fmaf(-EPSLN2, arg, fr3 + gj);
            part = fmaf(ex2f_(arg), C, part);
        }
    }

    __shared__ float red[256];
    red[threadIdx.x] = part;
    __syncthreads();
#pragma unroll
    for (int o = 128; o; o >>= 1) {
        if (threadIdx.x < o) red[threadIdx.x] += red[threadIdx.x + o];
        __syncthreads();
    }
    if (threadIdx.x == 0) d_partials[blockIdx.x] = red[0];
}

__global__ void reduce_kernel(float* __restrict__ out) {
    __shared__ float red[256];
    float v = 0.f;
    for (int i = threadIdx.x; i < 1024; i += 256) v += d_partials[i];
    red[threadIdx.x] = v;
    __syncthreads();
#pragma unroll
    for (int o = 128; o; o >>= 1) {
        if (threadIdx.x < o) red[threadIdx.x] += red[threadIdx.x + o];
        __syncthreads();
    }
    if (threadIdx.x == 0) out[0] = red[0] * 0.125f;
}

extern "C" void kernel_launch(void* const* d_in, const int* in_sizes, int n_in,
                              void* d_out, int out_size) {
    const float* preds = (const float*)d_in[0];
    const float* gts   = (const float*)d_in[1];
    float* out = (float*)d_out;

    prep_sort_kernel<<<BB * 2, 256>>>(preds, gts);
    half_boot<<<BB * 128, 256>>>(0);
    half_boot<<<BB * 128, 256>>>(1);
    for (int it = 1; it < 50; ++it) {
        half_fast<<<BB * 128, 256>>>(0);
        half_fast<<<BB * 128, 256>>>(1);
    }
    loss_kernel<<<BB * 128, 256>>>();
    reduce_kernel<<<1, 256>>>(out);
}